// round 3
// baseline (speedup 1.0000x reference)
#include <cuda_runtime.h>
#include <math.h>

#define Bn 128
#define Ln 400
#define Dn 1024
#define Cn 256

// Scratch (no cudaMalloc allowed): two ping-pong activation buffers [B, C, L]
// and transposed conv weights [ (i*3+k), o ] for the 3 conv layers.
__device__ float g_bufA[(size_t)Bn * Cn * Ln];
__device__ float g_bufB[(size_t)Bn * Cn * Ln];
__device__ float g_wt[3 * Cn * 3 * Cn];

// ---------------------------------------------------------------------------
// Weight transpose: W[o][i][k] (o*768 + i*3 + k) -> Wt[(i*3+k)*256 + o]
// ---------------------------------------------------------------------------
__global__ void wprep_kernel(const float* __restrict__ w, float* __restrict__ wt) {
    int idx = blockIdx.x * 256 + threadIdx.x;   // 0 .. 196607
    int o = idx / (Cn * 3);
    int r = idx - o * (Cn * 3);                 // i*3 + k
    wt[(size_t)r * Cn + o] = w[idx];
}

// ---------------------------------------------------------------------------
// Projection GEMM: H[b][n][l] = sum_k E[(b*400+l)][k] * Wl[k][n] + bl[n]
// M = B*L = 51200, K = 1024, N = 256. Tile 64x64, 64 threads, 8x8 per thread.
// ---------------------------------------------------------------------------
__global__ __launch_bounds__(64) void gemm_kernel(
    const float* __restrict__ E, const float* __restrict__ Wl,
    const float* __restrict__ bl, float* __restrict__ H) {
    __shared__ float Es[16][68];   // [k][m], row stride 272B (16B multiple)
    __shared__ float Ws[16][68];   // [k][n]
    const int m0 = blockIdx.x * 64;
    const int n0 = blockIdx.y * 64;
    const int tid = threadIdx.x;
    const int tm = tid >> 3, tn = tid & 7;

    float acc[8][8];
#pragma unroll
    for (int i = 0; i < 8; i++)
#pragma unroll
        for (int j = 0; j < 8; j++) acc[i][j] = 0.f;

    for (int k0 = 0; k0 < Dn; k0 += 16) {
        __syncthreads();
#pragma unroll
        for (int t = tid; t < 256; t += 64) {
            int m = t >> 2, kq = (t & 3) << 2;
            float4 e = *(const float4*)&E[(size_t)(m0 + m) * Dn + k0 + kq];
            Es[kq + 0][m] = e.x; Es[kq + 1][m] = e.y;
            Es[kq + 2][m] = e.z; Es[kq + 3][m] = e.w;
        }
#pragma unroll
        for (int t = tid; t < 256; t += 64) {
            int k = t >> 4, nq = (t & 15) << 2;
            *(float4*)&Ws[k][nq] = *(const float4*)&Wl[(size_t)(k0 + k) * Cn + n0 + nq];
        }
        __syncthreads();
#pragma unroll
        for (int k = 0; k < 16; k++) {
            float ev[8], wv[8];
            *(float4*)&ev[0] = *(const float4*)&Es[k][tm * 8];
            *(float4*)&ev[4] = *(const float4*)&Es[k][tm * 8 + 4];
            *(float4*)&wv[0] = *(const float4*)&Ws[k][tn * 8];
            *(float4*)&wv[4] = *(const float4*)&Ws[k][tn * 8 + 4];
#pragma unroll
            for (int i = 0; i < 8; i++)
#pragma unroll
                for (int j = 0; j < 8; j++) acc[i][j] += ev[i] * wv[j];
        }
    }

    // Store transposed into [B, C, L]. Thread's 8 m's are 8 consecutive l's
    // (never crossing a batch boundary since 400 % 8 == 0).
    const int mbase = m0 + tm * 8;
    const int bb = mbase / Ln;
    const int lb = mbase - bb * Ln;
#pragma unroll
    for (int nn = 0; nn < 8; nn++) {
        int n = n0 + tn * 8 + nn;
        float bnv = bl[n];
        float* dst = H + ((size_t)bb * Cn + n) * Ln + lb;
        float4 v0 = make_float4(acc[0][nn] + bnv, acc[1][nn] + bnv,
                                acc[2][nn] + bnv, acc[3][nn] + bnv);
        float4 v1 = make_float4(acc[4][nn] + bnv, acc[5][nn] + bnv,
                                acc[6][nn] + bnv, acc[7][nn] + bnv);
        *(float4*)dst = v0;
        *(float4*)(dst + 4) = v1;
    }
}

// ---------------------------------------------------------------------------
// Conv1d (k=3, dilation DIL, pad DIL) as implicit GEMM on [B, C, L].
// y[b,o,l] = bias[o] + sum_{i,k} w[o,i,k] * x[b,i,l+(k-1)*DIL]
// Block: 128 threads, tile O=64, L=64; per thread 4 O x 8 L.
// ---------------------------------------------------------------------------
template <int DIL, bool RELU>
__global__ __launch_bounds__(128) void conv_kernel(
    const float* __restrict__ X, const float* __restrict__ Wt,
    const float* __restrict__ bias, float* __restrict__ Y) {
    __shared__ float ws[48][64];   // [(i_local*3+k)][o]
    __shared__ float xs[16][72];   // [i_local][l + halo], row stride 288B

    const int l0 = blockIdx.x * 64;
    const int o0 = blockIdx.y * 64;
    const int b  = blockIdx.z;
    const int tid = threadIdx.x;
    const int ty = tid >> 3;     // 0..15 -> o
    const int tx = tid & 7;      // 0..7  -> l

    float acc[4][8];
#pragma unroll
    for (int i = 0; i < 4; i++)
#pragma unroll
        for (int j = 0; j < 8; j++) acc[i][j] = 0.f;

    const int XW = 64 + 2 * DIL;

    for (int i0 = 0; i0 < Cn; i0 += 16) {
        __syncthreads();
        // x tile with halo, zero-padded at sequence edges
        for (int idx = tid; idx < 16 * XW; idx += 128) {
            int i = idx / XW, c = idx - i * XW;
            int pos = l0 - DIL + c;
            float v = 0.f;
            if ((unsigned)pos < (unsigned)Ln)
                v = X[((size_t)b * Cn + i0 + i) * Ln + pos];
            xs[i][c] = v;
        }
        // weight tile: 48 rows x 64 o, coalesced from transposed layout
        {
            const float* wsrc = Wt + (size_t)i0 * 3 * Cn + o0;
            for (int idx = tid; idx < 48 * 64; idx += 128) {
                int r = idx >> 6, o = idx & 63;
                ws[r][o] = wsrc[(size_t)r * Cn + o];
            }
        }
        __syncthreads();

#pragma unroll
        for (int i = 0; i < 16; i++) {
            float xv[8 + 2 * DIL];
            const float* xr = &xs[i][tx * 8];
#pragma unroll
            for (int j = 0; j < 8 + 2 * DIL; j++) xv[j] = xr[j];
#pragma unroll
            for (int k = 0; k < 3; k++) {
                float4 w4 = *(const float4*)&ws[i * 3 + k][ty * 4];
                float wo[4] = {w4.x, w4.y, w4.z, w4.w};
#pragma unroll
                for (int oo = 0; oo < 4; oo++)
#pragma unroll
                    for (int ll = 0; ll < 8; ll++)
                        acc[oo][ll] += wo[oo] * xv[ll + k * DIL];
            }
        }
    }

#pragma unroll
    for (int oo = 0; oo < 4; oo++) {
        int o = o0 + ty * 4 + oo;
        float bo = bias[o];
        float* yr = Y + ((size_t)b * Cn + o) * Ln;
#pragma unroll
        for (int ll = 0; ll < 8; ll++) {
            int l = l0 + tx * 8 + ll;
            if (l < Ln) {
                float v = acc[oo][ll] + bo;
                if (RELU) v = fmaxf(v, 0.f);
                yr[l] = v;
            }
        }
    }
}

// ---------------------------------------------------------------------------
// LayerNorm over L=400 per (b,c) row, in place. Optional fused input ReLU.
// torch-style: unbiased std (ddof=1), divide by (std + eps).
// One warp per row.
// ---------------------------------------------------------------------------
template <bool RELU>
__global__ __launch_bounds__(256) void ln_kernel(
    float* __restrict__ X, const float* __restrict__ g,
    const float* __restrict__ be) {
    const int warp = threadIdx.x >> 5;
    const int lane = threadIdx.x & 31;
    const int row = blockIdx.x * 8 + warp;      // rows = B*C = 32768
    float* p = X + (size_t)row * Ln;

    float v[13];
    float s = 0.f;
#pragma unroll
    for (int j = 0; j < 13; j++) {
        int idx = j * 32 + lane;
        float x = (idx < Ln) ? p[idx] : 0.f;
        if (RELU) x = fmaxf(x, 0.f);
        v[j] = x;
        s += x;
    }
#pragma unroll
    for (int o = 16; o; o >>= 1) s += __shfl_xor_sync(0xffffffffu, s, o);
    const float mean = s * (1.f / Ln);

    float sq = 0.f;
#pragma unroll
    for (int j = 0; j < 13; j++) {
        int idx = j * 32 + lane;
        float d = (idx < Ln) ? (v[j] - mean) : 0.f;
        sq += d * d;
    }
#pragma unroll
    for (int o = 16; o; o >>= 1) sq += __shfl_xor_sync(0xffffffffu, sq, o);
    const float inv = 1.f / (sqrtf(sq * (1.f / (Ln - 1))) + 1e-6f);

#pragma unroll
    for (int j = 0; j < 13; j++) {
        int idx = j * 32 + lane;
        if (idx < Ln) p[idx] = g[idx] * ((v[j] - mean) * inv) + be[idx];
    }
}

// ---------------------------------------------------------------------------
// Final transpose: [B, C, L] -> [B, L, C]
// ---------------------------------------------------------------------------
__global__ __launch_bounds__(256) void transpose_kernel(
    const float* __restrict__ A, float* __restrict__ out) {
    __shared__ float t[32][33];
    const int b = blockIdx.z;
    const int l0 = blockIdx.x * 32;
    const int c0 = blockIdx.y * 32;
    const int tx = threadIdx.x, ty = threadIdx.y;
#pragma unroll
    for (int j = ty; j < 32; j += 8) {
        int c = c0 + j, l = l0 + tx;
        if (l < Ln) t[j][tx] = A[((size_t)b * Cn + c) * Ln + l];
    }
    __syncthreads();
#pragma unroll
    for (int j = ty; j < 32; j += 8) {
        int l = l0 + j, c = c0 + tx;
        if (l < Ln) out[((size_t)b * Ln + l) * Cn + c] = t[tx][j];
    }
}

// ---------------------------------------------------------------------------
// Host orchestration
// ---------------------------------------------------------------------------
static void run_net(float* x, float* y, const float* wt0, const float* b0,
                    const float* wt1, const float* b1, const float* wt2,
                    const float* b2, const float* g1, const float* be1) {
    dim3 cgrid(7, 4, Bn);
    conv_kernel<1, true><<<cgrid, 128>>>(x, wt0, b0, y);   // conv0 + ReLU
    ln_kernel<false><<<4096, 256>>>(y, g1, be1);           // inner LN
    conv_kernel<1, false><<<cgrid, 128>>>(y, wt1, b1, x);  // conv1
    conv_kernel<2, false><<<cgrid, 128>>>(x, wt2, b2, y);  // conv2 (dil 2)
}

extern "C" void kernel_launch(void* const* d_in, const int* in_sizes, int n_in,
                              void* d_out, int out_size) {
    const float* E   = (const float*)d_in[0];
    // d_in[1] = length (unused)
    const float* Wl  = (const float*)d_in[2];
    const float* bl  = (const float*)d_in[3];
    const float* w0  = (const float*)d_in[4];
    const float* b0  = (const float*)d_in[5];
    const float* w1  = (const float*)d_in[6];
    const float* b1  = (const float*)d_in[7];
    const float* w2  = (const float*)d_in[8];
    const float* b2  = (const float*)d_in[9];
    const float* g1  = (const float*)d_in[10];
    const float* be1 = (const float*)d_in[11];
    const float* g2  = (const float*)d_in[12];
    const float* be2 = (const float*)d_in[13];
    float* out = (float*)d_out;

    float *A, *Bb, *wt;
    cudaGetSymbolAddress((void**)&A, g_bufA);
    cudaGetSymbolAddress((void**)&Bb, g_bufB);
    cudaGetSymbolAddress((void**)&wt, g_wt);
    float* wt0 = wt;
    float* wt1 = wt + (size_t)Cn * 3 * Cn;
    float* wt2 = wt + (size_t)2 * Cn * 3 * Cn;

    wprep_kernel<<<768, 256>>>(w0, wt0);
    wprep_kernel<<<768, 256>>>(w1, wt1);
    wprep_kernel<<<768, 256>>>(w2, wt2);

    gemm_kernel<<<dim3(800, 4), 64>>>(E, Wl, bl, A);       // -> A [B,C,L]

    run_net(A, Bb, wt0, b0, wt1, b1, wt2, b2, g1, be1);    // net 1 -> Bb
    ln_kernel<true><<<4096, 256>>>(Bb, g2, be2);           // ReLU + outer LN
    run_net(Bb, A, wt0, b0, wt1, b1, wt2, b2, g1, be1);    // net 2 -> A
    run_net(A, Bb, wt0, b0, wt1, b1, wt2, b2, g1, be1);    // net 3 -> Bb
    run_net(Bb, A, wt0, b0, wt1, b1, wt2, b2, g1, be1);    // net 4 -> A

    transpose_kernel<<<dim3(13, 8, Bn), dim3(32, 8)>>>(A, out);
}

// round 4
// speedup vs baseline: 1.0526x; 1.0526x over previous
#include <cuda_runtime.h>
#include <math.h>

#define Bn 128
#define Ln 400
#define Dn 1024
#define Cn 256

// Scratch (no cudaMalloc allowed): two ping-pong activation buffers [B, C, L]
// and transposed conv weights [ (i*3+k), o ] for the 3 conv layers.
__device__ float g_bufA[(size_t)Bn * Cn * Ln];
__device__ float g_bufB[(size_t)Bn * Cn * Ln];
__device__ float g_wt[3 * Cn * 3 * Cn];

// ---------------------------------------------------------------------------
// Weight transpose: W[o][i][k] (o*768 + i*3 + k) -> Wt[(i*3+k)*256 + o]
// ---------------------------------------------------------------------------
__global__ void wprep_kernel(const float* __restrict__ w, float* __restrict__ wt) {
    int idx = blockIdx.x * 256 + threadIdx.x;   // 0 .. 196607
    int o = idx / (Cn * 3);
    int r = idx - o * (Cn * 3);                 // i*3 + k
    wt[(size_t)r * Cn + o] = w[idx];
}

// ---------------------------------------------------------------------------
// Projection GEMM: H[b][n][l] = sum_k E[(b*400+l)][k] * Wl[k][n] + bl[n]
// M = B*L = 51200, K = 1024, N = 256. Tile 64x64, 64 threads, 8x8 per thread.
// ---------------------------------------------------------------------------
__global__ __launch_bounds__(64) void gemm_kernel(
    const float* __restrict__ E, const float* __restrict__ Wl,
    const float* __restrict__ bl, float* __restrict__ H) {
    __shared__ float Es[16][68];   // [k][m], row stride 272B (16B multiple)
    __shared__ float Ws[16][68];   // [k][n]
    const int m0 = blockIdx.x * 64;
    const int n0 = blockIdx.y * 64;
    const int tid = threadIdx.x;
    const int tm = tid >> 3, tn = tid & 7;

    float acc[8][8];
#pragma unroll
    for (int i = 0; i < 8; i++)
#pragma unroll
        for (int j = 0; j < 8; j++) acc[i][j] = 0.f;

    for (int k0 = 0; k0 < Dn; k0 += 16) {
        __syncthreads();
#pragma unroll
        for (int t = tid; t < 256; t += 64) {
            int m = t >> 2, kq = (t & 3) << 2;
            float4 e = *(const float4*)&E[(size_t)(m0 + m) * Dn + k0 + kq];
            Es[kq + 0][m] = e.x; Es[kq + 1][m] = e.y;
            Es[kq + 2][m] = e.z; Es[kq + 3][m] = e.w;
        }
#pragma unroll
        for (int t = tid; t < 256; t += 64) {
            int k = t >> 4, nq = (t & 15) << 2;
            *(float4*)&Ws[k][nq] = *(const float4*)&Wl[(size_t)(k0 + k) * Cn + n0 + nq];
        }
        __syncthreads();
#pragma unroll
        for (int k = 0; k < 16; k++) {
            float ev[8], wv[8];
            *(float4*)&ev[0] = *(const float4*)&Es[k][tm * 8];
            *(float4*)&ev[4] = *(const float4*)&Es[k][tm * 8 + 4];
            *(float4*)&wv[0] = *(const float4*)&Ws[k][tn * 8];
            *(float4*)&wv[4] = *(const float4*)&Ws[k][tn * 8 + 4];
#pragma unroll
            for (int i = 0; i < 8; i++)
#pragma unroll
                for (int j = 0; j < 8; j++) acc[i][j] += ev[i] * wv[j];
        }
    }

    // Store transposed into [B, C, L]. Thread's 8 m's are 8 consecutive l's
    // (never crossing a batch boundary since 400 % 8 == 0).
    const int mbase = m0 + tm * 8;
    const int bb = mbase / Ln;
    const int lb = mbase - bb * Ln;
#pragma unroll
    for (int nn = 0; nn < 8; nn++) {
        int n = n0 + tn * 8 + nn;
        float bnv = bl[n];
        float* dst = H + ((size_t)bb * Cn + n) * Ln + lb;
        float4 v0 = make_float4(acc[0][nn] + bnv, acc[1][nn] + bnv,
                                acc[2][nn] + bnv, acc[3][nn] + bnv);
        float4 v1 = make_float4(acc[4][nn] + bnv, acc[5][nn] + bnv,
                                acc[6][nn] + bnv, acc[7][nn] + bnv);
        *(float4*)dst = v0;
        *(float4*)(dst + 4) = v1;
    }
}

// ---------------------------------------------------------------------------
// Conv1d (k=3, dilation DIL, pad DIL) as implicit GEMM on [B, C, L].
// y[b,o,l] = bias[o] + sum_{i,k} w[o,i,k] * x[b,i,l+(k-1)*DIL]
// Block: 128 threads, tile O=64, L=64; per thread 4 O x 8 L.
// ---------------------------------------------------------------------------
template <int DIL, bool RELU>
__global__ __launch_bounds__(128) void conv_kernel(
    const float* __restrict__ X, const float* __restrict__ Wt,
    const float* __restrict__ bias, float* __restrict__ Y) {
    __shared__ float ws[48][64];   // [(i_local*3+k)][o]
    __shared__ float xs[16][72];   // [i_local][l + halo], row stride 288B

    const int l0 = blockIdx.x * 64;
    const int o0 = blockIdx.y * 64;
    const int b  = blockIdx.z;
    const int tid = threadIdx.x;
    const int ty = tid >> 3;     // 0..15 -> o
    const int tx = tid & 7;      // 0..7  -> l

    float acc[4][8];
#pragma unroll
    for (int i = 0; i < 4; i++)
#pragma unroll
        for (int j = 0; j < 8; j++) acc[i][j] = 0.f;

    const int XW = 64 + 2 * DIL;

    for (int i0 = 0; i0 < Cn; i0 += 16) {
        __syncthreads();
        // x tile with halo, zero-padded at sequence edges
        for (int idx = tid; idx < 16 * XW; idx += 128) {
            int i = idx / XW, c = idx - i * XW;
            int pos = l0 - DIL + c;
            float v = 0.f;
            if ((unsigned)pos < (unsigned)Ln)
                v = X[((size_t)b * Cn + i0 + i) * Ln + pos];
            xs[i][c] = v;
        }
        // weight tile: 48 rows x 64 o, coalesced from transposed layout
        {
            const float* wsrc = Wt + (size_t)i0 * 3 * Cn + o0;
            for (int idx = tid; idx < 48 * 64; idx += 128) {
                int r = idx >> 6, o = idx & 63;
                ws[r][o] = wsrc[(size_t)r * Cn + o];
            }
        }
        __syncthreads();

#pragma unroll
        for (int i = 0; i < 16; i++) {
            float xv[8 + 2 * DIL];
            const float* xr = &xs[i][tx * 8];
#pragma unroll
            for (int j = 0; j < 8 + 2 * DIL; j++) xv[j] = xr[j];
#pragma unroll
            for (int k = 0; k < 3; k++) {
                float4 w4 = *(const float4*)&ws[i * 3 + k][ty * 4];
                float wo[4] = {w4.x, w4.y, w4.z, w4.w};
#pragma unroll
                for (int oo = 0; oo < 4; oo++)
#pragma unroll
                    for (int ll = 0; ll < 8; ll++)
                        acc[oo][ll] += wo[oo] * xv[ll + k * DIL];
            }
        }
    }

#pragma unroll
    for (int oo = 0; oo < 4; oo++) {
        int o = o0 + ty * 4 + oo;
        float bo = bias[o];
        float* yr = Y + ((size_t)b * Cn + o) * Ln;
#pragma unroll
        for (int ll = 0; ll < 8; ll++) {
            int l = l0 + tx * 8 + ll;
            if (l < Ln) {
                float v = acc[oo][ll] + bo;
                if (RELU) v = fmaxf(v, 0.f);
                yr[l] = v;
            }
        }
    }
}

// ---------------------------------------------------------------------------
// LayerNorm over L=400 per (b,c) row, in place. Optional fused input ReLU.
// torch-style: unbiased std (ddof=1), divide by (std + eps).
// One warp per row.
// ---------------------------------------------------------------------------
template <bool RELU>
__global__ __launch_bounds__(256) void ln_kernel(
    float* __restrict__ X, const float* __restrict__ g,
    const float* __restrict__ be) {
    const int warp = threadIdx.x >> 5;
    const int lane = threadIdx.x & 31;
    const int row = blockIdx.x * 8 + warp;      // rows = B*C = 32768
    float* p = X + (size_t)row * Ln;

    float v[13];
    float s = 0.f;
#pragma unroll
    for (int j = 0; j < 13; j++) {
        int idx = j * 32 + lane;
        float x = (idx < Ln) ? p[idx] : 0.f;
        if (RELU) x = fmaxf(x, 0.f);
        v[j] = x;
        s += x;
    }
#pragma unroll
    for (int o = 16; o; o >>= 1) s += __shfl_xor_sync(0xffffffffu, s, o);
    const float mean = s * (1.f / Ln);

    float sq = 0.f;
#pragma unroll
    for (int j = 0; j < 13; j++) {
        int idx = j * 32 + lane;
        float d = (idx < Ln) ? (v[j] - mean) : 0.f;
        sq += d * d;
    }
#pragma unroll
    for (int o = 16; o; o >>= 1) sq += __shfl_xor_sync(0xffffffffu, sq, o);
    const float inv = 1.f / (sqrtf(sq * (1.f / (Ln - 1))) + 1e-6f);

#pragma unroll
    for (int j = 0; j < 13; j++) {
        int idx = j * 32 + lane;
        if (idx < Ln) p[idx] = g[idx] * ((v[j] - mean) * inv) + be[idx];
    }
}

// ---------------------------------------------------------------------------
// Final transpose: [B, C, L] -> [B, L, C]
// ---------------------------------------------------------------------------
__global__ __launch_bounds__(256) void transpose_kernel(
    const float* __restrict__ A, float* __restrict__ out) {
    __shared__ float t[32][33];
    const int b = blockIdx.z;
    const int l0 = blockIdx.x * 32;
    const int c0 = blockIdx.y * 32;
    const int tx = threadIdx.x, ty = threadIdx.y;
#pragma unroll
    for (int j = ty; j < 32; j += 8) {
        int c = c0 + j, l = l0 + tx;
        if (l < Ln) t[j][tx] = A[((size_t)b * Cn + c) * Ln + l];
    }
    __syncthreads();
#pragma unroll
    for (int j = ty; j < 32; j += 8) {
        int l = l0 + j, c = c0 + tx;
        if (l < Ln) out[((size_t)b * Ln + l) * Cn + c] = t[tx][j];
    }
}

// ---------------------------------------------------------------------------
// Host orchestration
// ---------------------------------------------------------------------------
static void run_net(float* x, float* y, const float* wt0, const float* b0,
                    const float* wt1, const float* b1, const float* wt2,
                    const float* b2, const float* g1, const float* be1) {
    dim3 cgrid(7, 4, Bn);
    conv_kernel<1, true><<<cgrid, 128>>>(x, wt0, b0, y);   // conv0 + ReLU
    ln_kernel<false><<<4096, 256>>>(y, g1, be1);           // inner LN
    conv_kernel<1, false><<<cgrid, 128>>>(y, wt1, b1, x);  // conv1
    conv_kernel<2, false><<<cgrid, 128>>>(x, wt2, b2, y);  // conv2 (dil 2)
}

extern "C" void kernel_launch(void* const* d_in, const int* in_sizes, int n_in,
                              void* d_out, int out_size) {
    const float* E   = (const float*)d_in[0];
    // d_in[1] = length (unused)
    const float* Wl  = (const float*)d_in[2];
    const float* bl  = (const float*)d_in[3];
    const float* w0  = (const float*)d_in[4];
    const float* b0  = (const float*)d_in[5];
    const float* w1  = (const float*)d_in[6];
    const float* b1  = (const float*)d_in[7];
    const float* w2  = (const float*)d_in[8];
    const float* b2  = (const float*)d_in[9];
    const float* g1  = (const float*)d_in[10];
    const float* be1 = (const float*)d_in[11];
    const float* g2  = (const float*)d_in[12];
    const float* be2 = (const float*)d_in[13];
    float* out = (float*)d_out;

    float *A, *Bb, *wt;
    cudaGetSymbolAddress((void**)&A, g_bufA);
    cudaGetSymbolAddress((void**)&Bb, g_bufB);
    cudaGetSymbolAddress((void**)&wt, g_wt);
    float* wt0 = wt;
    float* wt1 = wt + (size_t)Cn * 3 * Cn;
    float* wt2 = wt + (size_t)2 * Cn * 3 * Cn;

    wprep_kernel<<<768, 256>>>(w0, wt0);
    wprep_kernel<<<768, 256>>>(w1, wt1);
    wprep_kernel<<<768, 256>>>(w2, wt2);

    gemm_kernel<<<dim3(800, 4), 64>>>(E, Wl, bl, A);       // -> A [B,C,L]

    run_net(A, Bb, wt0, b0, wt1, b1, wt2, b2, g1, be1);    // net 1 -> Bb
    ln_kernel<true><<<4096, 256>>>(Bb, g2, be2);           // ReLU + outer LN
    run_net(Bb, A, wt0, b0, wt1, b1, wt2, b2, g1, be1);    // net 2 -> A
    run_net(A, Bb, wt0, b0, wt1, b1, wt2, b2, g1, be1);    // net 3 -> Bb
    run_net(Bb, A, wt0, b0, wt1, b1, wt2, b2, g1, be1);    // net 4 -> A

    transpose_kernel<<<dim3(13, 8, Bn), dim3(32, 8)>>>(A, out);
}